// round 9
// baseline (speedup 1.0000x reference)
#include <cuda_runtime.h>
#include <math_constants.h>

#define B_CONST 4096
#define D_CONST 256
#define N_CONST 8192
#define GRID    256
#define TPB     512      // 16 warps/block ; 256*16 = 4096 pairs

// scratch (device globals — allocation forbidden; zero-initialized at load)
__device__ int g_ep[GRID];   // per-block launch counter (lockstep across blocks)
__device__ int g_zflag = 0;  // epoch stamp: "output zeroed by block 0"

__device__ __forceinline__ float pick4(float4 v, int s) {
    float r = v.x;
    if (s == 1) r = v.y;
    if (s == 2) r = v.z;
    if (s == 3) r = v.w;
    return r;
}

// dual-row warp argmax: first-occurrence tie-break (matches jnp.argmax)
__device__ __forceinline__ void argmax2(
    float4 p0, float4 p1, float4 q0, float4 q1, int c0, int c1,
    const unsigned F, float& m0, int& j0, float& m1, int& j1)
{
    float b0 = p0.x; int i0 = c0;
    if (p0.y > b0) { b0 = p0.y; i0 = c0 + 1; }
    if (p0.z > b0) { b0 = p0.z; i0 = c0 + 2; }
    if (p0.w > b0) { b0 = p0.w; i0 = c0 + 3; }
    if (p1.x > b0) { b0 = p1.x; i0 = c1;     }
    if (p1.y > b0) { b0 = p1.y; i0 = c1 + 1; }
    if (p1.z > b0) { b0 = p1.z; i0 = c1 + 2; }
    if (p1.w > b0) { b0 = p1.w; i0 = c1 + 3; }

    float b1 = q0.x; int i1 = c0;
    if (q0.y > b1) { b1 = q0.y; i1 = c0 + 1; }
    if (q0.z > b1) { b1 = q0.z; i1 = c0 + 2; }
    if (q0.w > b1) { b1 = q0.w; i1 = c0 + 3; }
    if (q1.x > b1) { b1 = q1.x; i1 = c1;     }
    if (q1.y > b1) { b1 = q1.y; i1 = c1 + 1; }
    if (q1.z > b1) { b1 = q1.z; i1 = c1 + 2; }
    if (q1.w > b1) { b1 = q1.w; i1 = c1 + 3; }

    #pragma unroll
    for (int off = 16; off; off >>= 1) {
        float o0 = __shfl_down_sync(F, b0, off);
        int   k0 = __shfl_down_sync(F, i0, off);
        float o1 = __shfl_down_sync(F, b1, off);
        int   k1 = __shfl_down_sync(F, i1, off);
        if (o0 > b0 || (o0 == b0 && k0 < i0)) { b0 = o0; i0 = k0; }
        if (o1 > b1 || (o1 == b1 && k1 < i1)) { b1 = o1; i1 = k1; }
    }
    m0 = __shfl_sync(F, b0, 0);  j0 = __shfl_sync(F, i0, 0);
    m1 = __shfl_sync(F, b1, 0);  j1 = __shfl_sync(F, i1, 0);
}

__global__ void __launch_bounds__(TPB)
fused_kernel(const float* __restrict__ a,
             const float* __restrict__ b,
             const int*   __restrict__ negc,
             float* __restrict__ out,   // [0]=loss, [1..256]=num_max
             int out_n) {
    const int tid  = threadIdx.x;
    const int bid  = blockIdx.x;
    const int warp = tid >> 5;
    const int lane = tid & 31;
    const unsigned F = 0xffffffffu;

    __shared__ int   s_e;
    __shared__ float s_sum[16];
    __shared__ int   s_j[32];     // 16 warps x 2 argmax indices

    if (tid == 0) s_e = *(volatile int*)&g_ep[bid] + 1;

    // ---- indices & all 8 row loads issued up front (MLP=8) ----
    const int arow = bid * 16 + warp;                 // pair index 0..4095
    const float* r0 = a + (size_t)arow * D_CONST;     // row i   = arow
    const float* r1 = b + (size_t)arow * D_CONST;     // row i+B

    // negatives' random columns; both rows of the pair share e1=arow, e2=arow+B
    int cA = negc[arow];
    cA += (cA >= arow) ? 1 : 0;
    cA += (cA >= arow + B_CONST) ? 1 : 0;
    int cB = negc[arow + B_CONST];
    cB += (cB >= arow) ? 1 : 0;
    cB += (cB >= arow + B_CONST) ? 1 : 0;
    const float* rA = (cA < B_CONST) ? (a + (size_t)cA * D_CONST)
                                     : (b + (size_t)(cA - B_CONST) * D_CONST);
    const float* rB = (cB < B_CONST) ? (a + (size_t)cB * D_CONST)
                                     : (b + (size_t)(cB - B_CONST) * D_CONST);

    const int c0 = lane * 4;
    const int c1 = 128 + lane * 4;
    float4 v00 = *reinterpret_cast<const float4*>(r0 + c0);
    float4 v01 = *reinterpret_cast<const float4*>(r0 + c1);
    float4 v10 = *reinterpret_cast<const float4*>(r1 + c0);
    float4 v11 = *reinterpret_cast<const float4*>(r1 + c1);
    float4 w00 = *reinterpret_cast<const float4*>(rA + c0);
    float4 w01 = *reinterpret_cast<const float4*>(rA + c1);
    float4 w10 = *reinterpret_cast<const float4*>(rB + c0);
    float4 w11 = *reinterpret_cast<const float4*>(rB + c1);

    // block 0: zero output (poisoned 0xAA), then stamp the flag
    if (bid == 0) {
        if (tid < out_n) out[tid] = 0.0f;
        __syncthreads();
        if (tid == 0) {
            __threadfence();
            *(volatile int*)&g_zflag = s_e;
        }
    }

    // ---- own-pair argmax (m0,j0 / m1,j1) and random-row argmax (jA,jB) ----
    float m0, m1, mr0, mr1;
    int j0, j1, jA, jB;
    argmax2(v00, v01, v10, v11, c0, c1, F, m0, j0, m1, j1);
    argmax2(w00, w01, w10, w11, c0, c1, F, mr0, jA, mr1, jB);

    // positives: pos_a = m0 - row_a[j1] ; pos_b = m1 - row_b[j0]
    float fa = __shfl_sync(F, (j1 < 128) ? pick4(v00, j1 & 3) : pick4(v01, j1 & 3),
                           (j1 >> 2) & 31);
    float fb = __shfl_sync(F, (j0 < 128) ? pick4(v10, j0 & 3) : pick4(v11, j0 & 3),
                           (j0 >> 2) & 31);
    // negatives: neg_a = m0 - row_a[jA] ; neg_b = m1 - row_b[jB]
    float ga = __shfl_sync(F, (jA < 128) ? pick4(v00, jA & 3) : pick4(v01, jA & 3),
                           (jA >> 2) & 31);
    float gb = __shfl_sync(F, (jB < 128) ? pick4(v10, jB & 3) : pick4(v11, jB & 3),
                           (jB >> 2) & 31);

    const float mdA = fmaxf(1.0f - (m0 - ga), 0.0f);
    const float mdB = fmaxf(1.0f - (m1 - gb), 0.0f);
    const float contrib = (m0 - fa) + (m1 - fb) + mdA * mdA + mdB * mdB;

    if (lane == 0) {
        s_sum[warp]         = contrib;
        s_j[warp * 2]       = j0;
        s_j[warp * 2 + 1]   = j1;
    }
    __syncthreads();

    // ---- warp 0 finishes the block: spin on zflag, atomics ----
    if (warp == 0) {
        const int e = s_e;
        volatile int* zf = &g_zflag;
        while (*zf < e) { }                      // output guaranteed zeroed

        atomicAdd(&out[1 + s_j[lane]], 1.0f);    // 32 hist adds (16 pairs)

        float v = (lane < 16) ? s_sum[lane] : 0.0f;
        #pragma unroll
        for (int off = 8; off; off >>= 1)
            v += __shfl_down_sync(F, v, off);
        if (lane == 0) {
            atomicAdd(&out[0], 0.5f * v);        // sum(...)/2
            *(volatile int*)&g_ep[bid] = e;      // advance launch counter
        }
    }
}

extern "C" void kernel_launch(void* const* d_in, const int* in_sizes, int n_in,
                              void* d_out, int out_size) {
    const float* a    = (const float*)d_in[0];   // out_a [4096,256] f32
    const float* b    = (const float*)d_in[1];   // out_b [4096,256] f32
    const int*   negc = (const int*)  d_in[2];   // neg_choice [8192] i32
    float* out = (float*)d_out;

    fused_kernel<<<GRID, TPB>>>(a, b, negc, out, out_size);
}

// round 10
// speedup vs baseline: 1.1510x; 1.1510x over previous
#include <cuda_runtime.h>
#include <math_constants.h>

#define B_CONST 4096
#define D_CONST 256
#define N_CONST 8192
#define GRID    512
#define TPB     256      // 8 warps/block ; 512*8 = 4096 pairs

// scratch (device globals — allocation forbidden; zero-initialized at load)
__device__ int g_ep[GRID];   // per-block launch counter
__device__ int g_zflag = 0;  // epoch stamp: "output zeroed by block 0"

__device__ __forceinline__ float pick4(float4 v, int s) {
    float r = v.x;
    if (s == 1) r = v.y;
    if (s == 2) r = v.z;
    if (s == 3) r = v.w;
    return r;
}

// order-preserving float -> uint key (no NaNs in input)
__device__ __forceinline__ unsigned fkey(float f) {
    unsigned u = __float_as_uint(f);
    return u ^ ((unsigned)((int)u >> 31) | 0x80000000u);
}

// per-lane best of 8 elements (first-occurrence within lane)
__device__ __forceinline__ void lane_best(float4 p0, float4 p1, int c0, int c1,
                                          float& best, int& bidx) {
    best = p0.x; bidx = c0;
    if (p0.y > best) { best = p0.y; bidx = c0 + 1; }
    if (p0.z > best) { best = p0.z; bidx = c0 + 2; }
    if (p0.w > best) { best = p0.w; bidx = c0 + 3; }
    if (p1.x > best) { best = p1.x; bidx = c1;     }
    if (p1.y > best) { best = p1.y; bidx = c1 + 1; }
    if (p1.z > best) { best = p1.z; bidx = c1 + 2; }
    if (p1.w > best) { best = p1.w; bidx = c1 + 3; }
}

// warp argmax via redux.sync (value exact; owner = lowest matching lane)
__device__ __forceinline__ void warp_argmax(float best, int bidx, unsigned F,
                                            float& m, int& j) {
    const unsigned k = fkey(best);
    const unsigned w = __reduce_max_sync(F, k);
    const unsigned bal = __ballot_sync(F, k == w);
    const int owner = __ffs(bal) - 1;
    m = __shfl_sync(F, best, owner);
    j = __shfl_sync(F, bidx, owner);
}

__global__ void __launch_bounds__(TPB)
fused_kernel(const float* __restrict__ a,
             const float* __restrict__ b,
             const int*   __restrict__ negc,
             float* __restrict__ out,   // [0]=loss, [1..256]=num_max
             int out_n) {
    const int tid  = threadIdx.x;
    const int bid  = blockIdx.x;
    const int warp = tid >> 5;
    const int lane = tid & 31;
    const unsigned F = 0xffffffffu;

    __shared__ int   s_e;
    __shared__ float s_sum[8];
    __shared__ int   s_j[16];     // 8 warps x 2 argmax indices

    if (tid == 0) s_e = *(volatile int*)&g_ep[bid] + 1;

    // ---- indices & all 8 row loads issued up front (MLP=8) ----
    const int arow = bid * 8 + warp;                  // pair index 0..4095
    const float* r0 = a + (size_t)arow * D_CONST;     // row i   = arow
    const float* r1 = b + (size_t)arow * D_CONST;     // row i+B

    int cA = negc[arow];
    cA += (cA >= arow) ? 1 : 0;
    cA += (cA >= arow + B_CONST) ? 1 : 0;
    int cB = negc[arow + B_CONST];
    cB += (cB >= arow) ? 1 : 0;
    cB += (cB >= arow + B_CONST) ? 1 : 0;
    const float* rA = (cA < B_CONST) ? (a + (size_t)cA * D_CONST)
                                     : (b + (size_t)(cA - B_CONST) * D_CONST);
    const float* rB = (cB < B_CONST) ? (a + (size_t)cB * D_CONST)
                                     : (b + (size_t)(cB - B_CONST) * D_CONST);

    const int c0 = lane * 4;
    const int c1 = 128 + lane * 4;
    float4 v00 = *reinterpret_cast<const float4*>(r0 + c0);
    float4 v01 = *reinterpret_cast<const float4*>(r0 + c1);
    float4 v10 = *reinterpret_cast<const float4*>(r1 + c0);
    float4 v11 = *reinterpret_cast<const float4*>(r1 + c1);
    float4 w00 = *reinterpret_cast<const float4*>(rA + c0);
    float4 w01 = *reinterpret_cast<const float4*>(rA + c1);
    float4 w10 = *reinterpret_cast<const float4*>(rB + c0);
    float4 w11 = *reinterpret_cast<const float4*>(rB + c1);

    // block 0: zero output (poisoned 0xAA), stamp flag
    if (bid == 0) {
        for (int i = tid; i < out_n; i += TPB) out[i] = 0.0f;
        __syncthreads();
        if (tid == 0) {
            __threadfence();
            *(volatile int*)&g_zflag = s_e;
        }
    }

    // ---- 4 warp argmaxes via redux ----
    float bl; int bi;
    float m0, m1, mA, mB;
    int   j0, j1, jA, jB;
    lane_best(v00, v01, c0, c1, bl, bi);  warp_argmax(bl, bi, F, m0, j0);
    lane_best(v10, v11, c0, c1, bl, bi);  warp_argmax(bl, bi, F, m1, j1);
    lane_best(w00, w01, c0, c1, bl, bi);  warp_argmax(bl, bi, F, mA, jA);
    lane_best(w10, w11, c0, c1, bl, bi);  warp_argmax(bl, bi, F, mB, jB);

    // positives: pos_a = m0 - row_a[j1] ; pos_b = m1 - row_b[j0]
    float fa = __shfl_sync(F, (j1 < 128) ? pick4(v00, j1 & 3) : pick4(v01, j1 & 3),
                           (j1 >> 2) & 31);
    float fb = __shfl_sync(F, (j0 < 128) ? pick4(v10, j0 & 3) : pick4(v11, j0 & 3),
                           (j0 >> 2) & 31);
    // negatives: neg_a = m0 - row_a[jA] ; neg_b = m1 - row_b[jB]
    float ga = __shfl_sync(F, (jA < 128) ? pick4(v00, jA & 3) : pick4(v01, jA & 3),
                           (jA >> 2) & 31);
    float gb = __shfl_sync(F, (jB < 128) ? pick4(v10, jB & 3) : pick4(v11, jB & 3),
                           (jB >> 2) & 31);

    const float mdA = fmaxf(1.0f - (m0 - ga), 0.0f);
    const float mdB = fmaxf(1.0f - (m1 - gb), 0.0f);
    const float contrib = (m0 - fa) + (m1 - fb) + mdA * mdA + mdB * mdB;

    if (lane == 0) {
        s_sum[warp]       = contrib;
        s_j[warp * 2]     = j0;
        s_j[warp * 2 + 1] = j1;
    }
    __syncthreads();

    // ---- warp 0 finishes the block ----
    if (warp == 0) {
        const int e = s_e;
        volatile int* zf = &g_zflag;
        while (*zf < e) { }                          // output guaranteed zeroed

        if (lane < 16)
            atomicAdd(&out[1 + s_j[lane]], 1.0f);    // hist (8 pairs)

        float v = (lane < 8) ? s_sum[lane] : 0.0f;
        #pragma unroll
        for (int off = 4; off; off >>= 1)
            v += __shfl_down_sync(F, v, off);
        if (lane == 0) {
            atomicAdd(&out[0], 0.5f * v);            // sum(...)/2
            *(volatile int*)&g_ep[bid] = e;          // advance launch counter
        }
    }
}

extern "C" void kernel_launch(void* const* d_in, const int* in_sizes, int n_in,
                              void* d_out, int out_size) {
    const float* a    = (const float*)d_in[0];   // out_a [4096,256] f32
    const float* b    = (const float*)d_in[1];   // out_b [4096,256] f32
    const int*   negc = (const int*)  d_in[2];   // neg_choice [8192] i32
    float* out = (float*)d_out;

    fused_kernel<<<GRID, TPB>>>(a, b, negc, out, out_size);
}